// round 7
// baseline (speedup 1.0000x reference)
#include <cuda_runtime.h>
#include <cuda_fp16.h>

#define D 16
#define GBLK 64

// Scratch (allocation-free rule: __device__ globals). uint4-typed for 16B alignment.
__device__ float g_MW[4096];              // MW[j][k][l] = sum_n Wc1[j,n] * M[n,k,l]
__device__ float g_bb[16];                // bb[j] = bc1[j] + sum_n Wc1[j,n]*Boff[n]
__device__ uint4 g_E3h[20000 * 2];        // fp16 MLP output per gene
__device__ uint4 g_UWh[20000 * 32];       // fp16, uint4 at [g*32 + h*16 + j] = UW[g][j][8h..8h+7]

// ---- packed f32x2 helpers (sm_103a FFMA2 path) ----
__device__ __forceinline__ unsigned long long pk2(float a, float b) {
    unsigned long long r;
    asm("mov.b64 %0, {%1, %2};" : "=l"(r) : "f"(a), "f"(b));
    return r;
}
__device__ __forceinline__ unsigned long long fma2(unsigned long long a,
                                                   unsigned long long b,
                                                   unsigned long long c) {
    unsigned long long d;
    asm("fma.rn.f32x2 %0, %1, %2, %3;" : "=l"(d) : "l"(a), "l"(b), "l"(c));
    return d;
}
__device__ __forceinline__ float2 upk2(unsigned long long v) {
    float2 f;
    asm("mov.b64 {%0, %1}, %2;" : "=f"(f.x), "=f"(f.y) : "l"(v));
    return f;
}

// ---------------------------------------------------------------------------
// Kernel 1 (fused): blocks 0..15 compute MW[j]+bb; blocks 16.. run gene MLP
// with one thread per gene (16-way ILP per layer, broadcast LDS weights).
// ---------------------------------------------------------------------------
__global__ void k_pre(const float* __restrict__ BW, const float* __restrict__ BD,
                      const float* __restrict__ Wc1, const float* __restrict__ bc1,
                      const float* __restrict__ Boff,
                      const float* __restrict__ emb,
                      const float* __restrict__ W1, const float* __restrict__ b1,
                      const float* __restrict__ W2, const float* __restrict__ b2,
                      const float* __restrict__ W3, const float* __restrict__ b3,
                      int genes) {
    int t = threadIdx.x;

    if (blockIdx.x < 16) {
        __shared__ float sBW[4096], sBD[256], sWc1[256];
        {
            const float4* s = (const float4*)BW;
            float4* d = (float4*)sBW;
#pragma unroll
            for (int q = 0; q < 4; q++) d[t + 256 * q] = s[t + 256 * q];
            if (t < 64)       ((float4*)sBD)[t]       = ((const float4*)BD)[t];
            else if (t < 128) ((float4*)sWc1)[t - 64] = ((const float4*)Wc1)[t - 64];
        }
        __syncthreads();

        int j = blockIdx.x;
        int k = t >> 4, l = t & 15;
        float s = 0.f;
#pragma unroll
        for (int n = 0; n < 16; n++) {
            float wjn = sWc1[j * 16 + n];
#pragma unroll
            for (int m = 0; m < 16; m++) {
                float p = wjn * sBD[n * 16 + m];
                s = fmaf(p * sBW[n * 256 + m * 16 + k], sBW[m * 256 + n * 16 + l], s);
            }
        }
        g_MW[j * 256 + t] = s;

        if (blockIdx.x == 0 && t < 16) {
            float b = bc1[t];
#pragma unroll
            for (int n = 0; n < 16; n++) b = fmaf(sWc1[t * 16 + n], Boff[n], b);
            g_bb[t] = b;
        }
        return;
    }

    __shared__ float sW1[256], sW2[256], sW3[256], sb[48];
    if (t < 64)        ((float4*)sW1)[t]       = ((const float4*)W1)[t];
    else if (t < 128)  ((float4*)sW2)[t - 64]  = ((const float4*)W2)[t - 64];
    else if (t < 192)  ((float4*)sW3)[t - 128] = ((const float4*)W3)[t - 128];
    else if (t < 208) { int i = t - 192; sb[i] = b1[i]; sb[16 + i] = b2[i]; sb[32 + i] = b3[i]; }
    __syncthreads();

    int g = (blockIdx.x - 16) * 256 + t;
    if (g >= genes) return;

    float v[16], h[16], o[16];
    {
        const float4* ep = (const float4*)(emb + (size_t)g * 16);
        float4 a = ep[0], b = ep[1], c = ep[2], dd = ep[3];
        v[0]=a.x; v[1]=a.y; v[2]=a.z; v[3]=a.w;
        v[4]=b.x; v[5]=b.y; v[6]=b.z; v[7]=b.w;
        v[8]=c.x; v[9]=c.y; v[10]=c.z; v[11]=c.w;
        v[12]=dd.x; v[13]=dd.y; v[14]=dd.z; v[15]=dd.w;
    }
#pragma unroll
    for (int i = 0; i < 16; i++) {
        float s = sb[i];
#pragma unroll
        for (int jj = 0; jj < 16; jj++) s = fmaf(sW1[i * 16 + jj], v[jj], s);
        h[i] = fmaxf(s, 0.f);
    }
#pragma unroll
    for (int i = 0; i < 16; i++) {
        float s = sb[16 + i];
#pragma unroll
        for (int jj = 0; jj < 16; jj++) s = fmaf(sW2[i * 16 + jj], h[jj], s);
        o[i] = fmaxf(s, 0.f);
    }
#pragma unroll
    for (int i = 0; i < 16; i++) {
        float s = sb[32 + i];
#pragma unroll
        for (int jj = 0; jj < 16; jj++) s = fmaf(sW3[i * 16 + jj], o[jj], s);
        v[i] = s;   // no relu on layer 3
    }

    uint4 hv[2];
    unsigned* hw = (unsigned*)hv;
#pragma unroll
    for (int q = 0; q < 8; q++) {
        __half2 p = __floats2half2_rn(v[2 * q], v[2 * q + 1]);
        hw[q] = *(unsigned*)&p;
    }
    g_E3h[(size_t)g * 2 + 0] = hv[0];
    g_E3h[(size_t)g * 2 + 1] = hv[1];
}

// ---------------------------------------------------------------------------
// Kernel 2: UW[g,j,k] = sum_l MW[j,k,l]*E3[g,l], fp16 in/out, packed f32x2 FMA.
// 64 genes/block; thread owns (j, kchunk c) with 32 packed MW weights in regs.
// ---------------------------------------------------------------------------
__global__ void k_uw(int genes) {
    __shared__ float sv[GBLK * 17];
    int t = threadIdx.x;
    int base = blockIdx.x * GBLK;

    int j = t & 15;
    int c = (t >> 4) & 3;
    int sg = t >> 6;

    // packed MW: mwa[l] = (MW[j][4c][l], MW[j][4c+1][l]), mwb[l] = (MW[j][4c+2][l], MW[j][4c+3][l])
    unsigned long long mwa[16], mwb[16];
    {
        const float4* mp = (const float4*)(g_MW + j * 256 + c * 64);
        float m0[16], m1[16], m2[16], m3[16];
#pragma unroll
        for (int q = 0; q < 4; q++) {
            float4 a = mp[q], b = mp[4 + q], cc = mp[8 + q], d = mp[12 + q];
            m0[q*4+0]=a.x;  m0[q*4+1]=a.y;  m0[q*4+2]=a.z;  m0[q*4+3]=a.w;
            m1[q*4+0]=b.x;  m1[q*4+1]=b.y;  m1[q*4+2]=b.z;  m1[q*4+3]=b.w;
            m2[q*4+0]=cc.x; m2[q*4+1]=cc.y; m2[q*4+2]=cc.z; m2[q*4+3]=cc.w;
            m3[q*4+0]=d.x;  m3[q*4+1]=d.y;  m3[q*4+2]=d.z;  m3[q*4+3]=d.w;
        }
#pragma unroll
        for (int l = 0; l < 16; l++) {
            mwa[l] = pk2(m0[l], m1[l]);
            mwb[l] = pk2(m2[l], m3[l]);
        }
    }

    // stage E3 (fp16 -> fp32 shared): threads 0..127, one uint4 (8 halves) each
    if (t < 128) {
        int gl = t >> 1, part = t & 1;
        int g = base + gl;
        uint4 hv = (g < genes) ? g_E3h[(size_t)g * 2 + part] : make_uint4(0u, 0u, 0u, 0u);
        unsigned* hw = &hv.x;
#pragma unroll
        for (int q = 0; q < 4; q++) {
            float2 f = __half22float2(*(__half2*)&hw[q]);
            sv[gl * 17 + part * 8 + q * 2 + 0] = f.x;
            sv[gl * 17 + part * 8 + q * 2 + 1] = f.y;
        }
    }
    __syncthreads();

    uint2* outp = (uint2*)g_UWh;
#pragma unroll
    for (int gi = 0; gi < 16; gi++) {
        int gl = gi * 4 + sg;
        int g = base + gl;
        unsigned long long u01 = 0ull, u23 = 0ull;
#pragma unroll
        for (int l = 0; l < 16; l++) {
            float ev = sv[gl * 17 + l];
            unsigned long long ev2 = pk2(ev, ev);
            u01 = fma2(mwa[l], ev2, u01);
            u23 = fma2(mwb[l], ev2, u23);
        }
        if (g < genes) {
            float2 f01 = upk2(u01), f23 = upk2(u23);
            __half2 h01 = __floats2half2_rn(f01.x, f01.y);
            __half2 h23 = __floats2half2_rn(f23.x, f23.y);
            uint2 v;
            v.x = *(unsigned*)&h01;
            v.y = *(unsigned*)&h23;
            // uint4-friendly layout: uint2 index = g*64 + (c>>1)*32 + j*2 + (c&1)
            outp[(size_t)g * 64 + (c >> 1) * 32 + j * 2 + (c & 1)] = v;
        }
    }
}

// ---------------------------------------------------------------------------
// Kernel 3: main. 4 rows per 16-lane group (64 rows/block); lane j owns unit j.
//   y_j = relu(E3h[x0] . UWh[x1,j,:] + bb[j]); out = sum_j Wc2[j]*y_j + bc2 + sum(phenos)
// ---------------------------------------------------------------------------
__global__ void k_main(const int* __restrict__ x, const float* __restrict__ phenos,
                       const float* __restrict__ Wc2, const float* __restrict__ bc2,
                       float* __restrict__ out) {
    int t = threadIdx.x;
    int j = t & 15;
    int grp = t >> 4;
    int rbase = blockIdx.x * 64 + grp;

    float bbj = g_bb[j];
    float wc = Wc2[j];
    float acc[4];

#pragma unroll
    for (int r = 0; r < 4; r++) {
        int row = rbase + 16 * r;
        int2 xi = ((const int2*)x)[row];
        const uint4* E = g_E3h + (size_t)xi.x * 2;
        uint4 e0 = E[0], e1 = E[1];
        const uint4* U = g_UWh + (size_t)xi.y * 32;
        uint4 ua = U[j], ub = U[16 + j];

        float z = bbj;
        unsigned ue[8] = {e0.x, e0.y, e0.z, e0.w, e1.x, e1.y, e1.z, e1.w};
        unsigned uu[8] = {ua.x, ua.y, ua.z, ua.w, ub.x, ub.y, ub.z, ub.w};
#pragma unroll
        for (int q = 0; q < 8; q++) {
            float2 a = __half22float2(*(__half2*)&ue[q]);
            float2 u = __half22float2(*(__half2*)&uu[q]);
            z = fmaf(a.x, u.x, z);
            z = fmaf(a.y, u.y, z);
        }
        acc[r] = fmaxf(z, 0.f) * wc;
    }

#pragma unroll
    for (int m = 8; m >= 1; m >>= 1) {
#pragma unroll
        for (int r = 0; r < 4; r++)
            acc[r] += __shfl_xor_sync(0xffffffffu, acc[r], m);
    }

    if (j == 0) {
        float bc = bc2[0];
#pragma unroll
        for (int r = 0; r < 4; r++) {
            int row = rbase + 16 * r;
            float2 p = ((const float2*)phenos)[row];
            out[row] = acc[r] + bc + p.x + p.y;
        }
    }
}

// ---------------------------------------------------------------------------
extern "C" void kernel_launch(void* const* d_in, const int* in_sizes, int n_in,
                              void* d_out, int out_size) {
    const int*   x      = (const int*)d_in[0];
    const float* phenos = (const float*)d_in[1];
    const float* emb    = (const float*)d_in[2];
    const float* W1 = (const float*)d_in[3],  *b1 = (const float*)d_in[4];
    const float* W2 = (const float*)d_in[5],  *b2 = (const float*)d_in[6];
    const float* W3 = (const float*)d_in[7],  *b3 = (const float*)d_in[8];
    const float* BW = (const float*)d_in[9],  *BD = (const float*)d_in[10];
    const float* Boff = (const float*)d_in[11];
    const float* Wc1 = (const float*)d_in[12], *bc1 = (const float*)d_in[13];
    const float* Wc2 = (const float*)d_in[14], *bc2 = (const float*)d_in[15];
    float* out = (float*)d_out;

    int rows  = in_sizes[0] / 2;     // 262144
    int genes = in_sizes[2] / D;     // 20000

    int eblocks = (genes + 255) / 256;                // 79
    k_pre<<<16 + eblocks, 256>>>(BW, BD, Wc1, bc1, Boff, emb,
                                 W1, b1, W2, b2, W3, b3, genes);
    k_uw<<<(genes + GBLK - 1) / GBLK, 256>>>(genes);
    k_main<<<rows / 64, 256>>>(x, phenos, Wc2, bc2, out);
}

// round 8
// speedup vs baseline: 1.0122x; 1.0122x over previous
#include <cuda_runtime.h>
#include <cuda_fp16.h>

#define D 16
#define GBLK 64

// Scratch (allocation-free rule: __device__ globals). uint4-typed for 16B alignment.
__device__ float g_MW[4096];              // MW[j][k][l] = sum_n Wc1[j,n] * M[n,k,l]
__device__ float g_bb[16];                // bb[j] = bc1[j] + sum_n Wc1[j,n]*Boff[n]
__device__ float g_E3f[20000 * 16];       // fp32 MLP output per gene (input to k_uw)
__device__ uint4 g_E3h[20000 * 2];        // fp16 MLP output per gene (input to k_main)
__device__ uint4 g_UWh[20000 * 32];       // fp16: uint2 at [g*64 + c*16 + j] = UW[g][j][4c..4c+3]

// ---------------------------------------------------------------------------
// Kernel 1 (fused): blocks 0..15 compute MW[j]+bb; blocks 16.. run gene MLP
// with TWO threads per gene (8 outputs each, halves exchanged via shfl_xor).
// ---------------------------------------------------------------------------
__global__ void k_pre(const float* __restrict__ BW, const float* __restrict__ BD,
                      const float* __restrict__ Wc1, const float* __restrict__ bc1,
                      const float* __restrict__ Boff,
                      const float* __restrict__ emb,
                      const float* __restrict__ W1, const float* __restrict__ b1,
                      const float* __restrict__ W2, const float* __restrict__ b2,
                      const float* __restrict__ W3, const float* __restrict__ b3,
                      int genes) {
    int t = threadIdx.x;

    if (blockIdx.x < 16) {
        // ---- MW block: stage operands in shared (one coalesced burst) ----
        __shared__ float sBW[4096], sBD[256], sWc1[256];
        {
            const float4* s = (const float4*)BW;
            float4* d = (float4*)sBW;
#pragma unroll
            for (int q = 0; q < 4; q++) d[t + 256 * q] = s[t + 256 * q];
            if (t < 64)       ((float4*)sBD)[t]       = ((const float4*)BD)[t];
            else if (t < 128) ((float4*)sWc1)[t - 64] = ((const float4*)Wc1)[t - 64];
        }
        __syncthreads();

        int j = blockIdx.x;
        int k = t >> 4, l = t & 15;
        float s = 0.f;
#pragma unroll
        for (int n = 0; n < 16; n++) {
            float wjn = sWc1[j * 16 + n];
#pragma unroll
            for (int m = 0; m < 16; m++) {
                float p = wjn * sBD[n * 16 + m];
                s = fmaf(p * sBW[n * 256 + m * 16 + k], sBW[m * 256 + n * 16 + l], s);
            }
        }
        g_MW[j * 256 + t] = s;

        if (blockIdx.x == 0 && t < 16) {
            float b = bc1[t];
#pragma unroll
            for (int n = 0; n < 16; n++) b = fmaf(sWc1[t * 16 + n], Boff[n], b);
            g_bb[t] = b;
        }
        return;
    }

    // ---- E3 blocks: 128 genes/block, 2 threads per gene ----
    __shared__ float sW1[256], sW2[256], sW3[256], sb[48];
    if (t < 64)        ((float4*)sW1)[t]       = ((const float4*)W1)[t];
    else if (t < 128)  ((float4*)sW2)[t - 64]  = ((const float4*)W2)[t - 64];
    else if (t < 192)  ((float4*)sW3)[t - 128] = ((const float4*)W3)[t - 128];
    else if (t < 208) { int i = t - 192; sb[i] = b1[i]; sb[16 + i] = b2[i]; sb[32 + i] = b3[i]; }
    __syncthreads();

    int gl = t >> 1;            // gene within block (0..127)
    int hf = t & 1;             // which half of the outputs this thread owns
    int g = (blockIdx.x - 16) * 128 + gl;
    if (g >= genes) return;

    float v[16];
    {
        const float4* ep = (const float4*)(emb + (size_t)g * 16);
        float4 a = ep[0], b = ep[1], c = ep[2], dd = ep[3];
        v[0]=a.x; v[1]=a.y; v[2]=a.z; v[3]=a.w;
        v[4]=b.x; v[5]=b.y; v[6]=b.z; v[7]=b.w;
        v[8]=c.x; v[9]=c.y; v[10]=c.z; v[11]=c.w;
        v[12]=dd.x; v[13]=dd.y; v[14]=dd.z; v[15]=dd.w;
    }

    float mine[8], full[16];
    // ---- layer 1 ----
#pragma unroll
    for (int ii = 0; ii < 8; ii++) {
        int i = hf * 8 + ii;
        float s = sb[i];
#pragma unroll
        for (int jj = 0; jj < 16; jj++) s = fmaf(sW1[i * 16 + jj], v[jj], s);
        mine[ii] = fmaxf(s, 0.f);
    }
#pragma unroll
    for (int ii = 0; ii < 8; ii++) {
        full[hf * 8 + ii] = mine[ii];
        full[(1 - hf) * 8 + ii] = __shfl_xor_sync(0xffffffffu, mine[ii], 1);
    }
    // ---- layer 2 ----
#pragma unroll
    for (int ii = 0; ii < 8; ii++) {
        int i = hf * 8 + ii;
        float s = sb[16 + i];
#pragma unroll
        for (int jj = 0; jj < 16; jj++) s = fmaf(sW2[i * 16 + jj], full[jj], s);
        mine[ii] = fmaxf(s, 0.f);
    }
#pragma unroll
    for (int ii = 0; ii < 8; ii++) {
        v[hf * 8 + ii] = mine[ii];
        v[(1 - hf) * 8 + ii] = __shfl_xor_sync(0xffffffffu, mine[ii], 1);
    }
    // ---- layer 3 (no relu) ----
#pragma unroll
    for (int ii = 0; ii < 8; ii++) {
        int i = hf * 8 + ii;
        float s = sb[32 + i];
#pragma unroll
        for (int jj = 0; jj < 16; jj++) s = fmaf(sW3[i * 16 + jj], v[jj], s);
        mine[ii] = s;
    }

    // stores: this thread owns elements [hf*8, hf*8+8)
    float4* fp = (float4*)(g_E3f + (size_t)g * 16 + hf * 8);
    fp[0] = make_float4(mine[0], mine[1], mine[2], mine[3]);
    fp[1] = make_float4(mine[4], mine[5], mine[6], mine[7]);

    uint4 hv;
    unsigned* hw = &hv.x;
#pragma unroll
    for (int q = 0; q < 4; q++) {
        __half2 p = __floats2half2_rn(mine[2 * q], mine[2 * q + 1]);
        hw[q] = *(unsigned*)&p;
    }
    g_E3h[(size_t)g * 2 + hf] = hv;
}

// ---------------------------------------------------------------------------
// Kernel 2: UW[g,j,k] = sum_l MW[j,k,l]*E3[g,l], fp16 output.  (R6 version)
// 64 genes/block; thread owns (j, kchunk) with 64 MW weights in registers.
// ---------------------------------------------------------------------------
__global__ void k_uw(int genes) {
    __shared__ float sv[GBLK * 17];
    int t = threadIdx.x;
    int base = blockIdx.x * GBLK;

    {
        int fidx = base * 4 + t;
        int gl = t >> 2, q = t & 3;
        float4 v = make_float4(0.f, 0.f, 0.f, 0.f);
        if (fidx < genes * 4) v = ((const float4*)g_E3f)[fidx];
        sv[gl * 17 + q * 4 + 0] = v.x;
        sv[gl * 17 + q * 4 + 1] = v.y;
        sv[gl * 17 + q * 4 + 2] = v.z;
        sv[gl * 17 + q * 4 + 3] = v.w;
    }

    int j = t & 15;
    int c = (t >> 4) & 3;
    int sg = t >> 6;

    float mw[64];
    {
        const float4* mp = (const float4*)(g_MW + j * 256 + c * 64);
#pragma unroll
        for (int q = 0; q < 16; q++) {
            float4 m4 = mp[q];
            mw[q*4+0]=m4.x; mw[q*4+1]=m4.y; mw[q*4+2]=m4.z; mw[q*4+3]=m4.w;
        }
    }
    __syncthreads();

    uint2* outp = (uint2*)g_UWh;
#pragma unroll
    for (int gi = 0; gi < 16; gi++) {
        int gl = gi * 4 + sg;
        int g = base + gl;
        float u0 = 0.f, u1 = 0.f, u2 = 0.f, u3 = 0.f;
#pragma unroll
        for (int l = 0; l < 16; l++) {
            float ev = sv[gl * 17 + l];
            u0 = fmaf(mw[0  + l], ev, u0);
            u1 = fmaf(mw[16 + l], ev, u1);
            u2 = fmaf(mw[32 + l], ev, u2);
            u3 = fmaf(mw[48 + l], ev, u3);
        }
        if (g < genes) {
            __half2 h01 = __floats2half2_rn(u0, u1);
            __half2 h23 = __floats2half2_rn(u2, u3);
            uint2 v;
            v.x = *(unsigned*)&h01;
            v.y = *(unsigned*)&h23;
            outp[(size_t)g * 64 + c * 16 + j] = v;
        }
    }
}

// ---------------------------------------------------------------------------
// Kernel 3: main. 2 rows per 16-lane group (4 rows/warp).  (R6 version)
// ---------------------------------------------------------------------------
__global__ void k_main(const int* __restrict__ x, const float* __restrict__ phenos,
                       const float* __restrict__ Wc2, const float* __restrict__ bc2,
                       float* __restrict__ out) {
    int t = threadIdx.x;
    int j = t & 15;
    int grp = t >> 4;
    int row0 = blockIdx.x * 32 + grp;
    int row1 = row0 + 16;

    int2 xa = ((const int2*)x)[row0];
    int2 xb = ((const int2*)x)[row1];

    const uint4* Ea = g_E3h + (size_t)xa.x * 2;
    const uint4* Eb = g_E3h + (size_t)xb.x * 2;
    uint4 ea0 = Ea[0], ea1 = Ea[1];
    uint4 eb0 = Eb[0], eb1 = Eb[1];
    const uint2* Ua = (const uint2*)(g_UWh + (size_t)xa.y * 32);
    const uint2* Ub = (const uint2*)(g_UWh + (size_t)xb.y * 32);
    uint2 qa0 = Ua[j], qa1 = Ua[16 + j], qa2 = Ua[32 + j], qa3 = Ua[48 + j];
    uint2 qb0 = Ub[j], qb1 = Ub[16 + j], qb2 = Ub[32 + j], qb3 = Ub[48 + j];

    float bbj = g_bb[j];
    float z0 = bbj, z1 = bbj;
    {
        unsigned uea[8] = {ea0.x, ea0.y, ea0.z, ea0.w, ea1.x, ea1.y, ea1.z, ea1.w};
        unsigned uua[8] = {qa0.x, qa0.y, qa1.x, qa1.y, qa2.x, qa2.y, qa3.x, qa3.y};
        unsigned ueb[8] = {eb0.x, eb0.y, eb0.z, eb0.w, eb1.x, eb1.y, eb1.z, eb1.w};
        unsigned uub[8] = {qb0.x, qb0.y, qb1.x, qb1.y, qb2.x, qb2.y, qb3.x, qb3.y};
#pragma unroll
        for (int q = 0; q < 8; q++) {
            float2 a = __half22float2(*(__half2*)&uea[q]);
            float2 u = __half22float2(*(__half2*)&uua[q]);
            z0 = fmaf(a.x, u.x, z0);
            z0 = fmaf(a.y, u.y, z0);
            float2 b = __half22float2(*(__half2*)&ueb[q]);
            float2 w = __half22float2(*(__half2*)&uub[q]);
            z1 = fmaf(b.x, w.x, z1);
            z1 = fmaf(b.y, w.y, z1);
        }
    }

    float wc = Wc2[j];
    float acc0 = fmaxf(z0, 0.f) * wc;
    float acc1 = fmaxf(z1, 0.f) * wc;
#pragma unroll
    for (int m = 8; m >= 1; m >>= 1) {
        acc0 += __shfl_xor_sync(0xffffffffu, acc0, m);
        acc1 += __shfl_xor_sync(0xffffffffu, acc1, m);
    }

    if (j == 0) {
        float bc = bc2[0];
        float2 p0 = ((const float2*)phenos)[row0];
        float2 p1 = ((const float2*)phenos)[row1];
        out[row0] = acc0 + bc + p0.x + p0.y;
        out[row1] = acc1 + bc + p1.x + p1.y;
    }
}

// ---------------------------------------------------------------------------
extern "C" void kernel_launch(void* const* d_in, const int* in_sizes, int n_in,
                              void* d_out, int out_size) {
    const int*   x      = (const int*)d_in[0];
    const float* phenos = (const float*)d_in[1];
    const float* emb    = (const float*)d_in[2];
    const float* W1 = (const float*)d_in[3],  *b1 = (const float*)d_in[4];
    const float* W2 = (const float*)d_in[5],  *b2 = (const float*)d_in[6];
    const float* W3 = (const float*)d_in[7],  *b3 = (const float*)d_in[8];
    const float* BW = (const float*)d_in[9],  *BD = (const float*)d_in[10];
    const float* Boff = (const float*)d_in[11];
    const float* Wc1 = (const float*)d_in[12], *bc1 = (const float*)d_in[13];
    const float* Wc2 = (const float*)d_in[14], *bc2 = (const float*)d_in[15];
    float* out = (float*)d_out;

    int rows  = in_sizes[0] / 2;     // 262144
    int genes = in_sizes[2] / D;     // 20000

    int eblocks = (genes + 127) / 128;                // 157
    k_pre<<<16 + eblocks, 256>>>(BW, BD, Wc1, bc1, Boff, emb,
                                 W1, b1, W2, b2, W3, b3, genes);
    k_uw<<<(genes + GBLK - 1) / GBLK, 256>>>(genes);
    k_main<<<rows / 32, 256>>>(x, phenos, Wc2, bc2, out);
}

// round 9
// speedup vs baseline: 1.0677x; 1.0548x over previous
#include <cuda_runtime.h>
#include <cuda_fp16.h>

#define D 16
#define GBLK 64

// Scratch (allocation-free rule: __device__ globals). uint4-typed for 16B alignment.
__device__ float g_MW[4096];              // MW[j][k][l] = sum_n Wc1[j,n] * M[n,k,l]
__device__ float g_bb[16];                // bb[j] = bc1[j] + sum_n Wc1[j,n]*Boff[n]
__device__ float g_E3f[20000 * 16];       // fp32 MLP output per gene (input to k_uw)
__device__ uint4 g_E3h[20000 * 2];        // fp16 MLP output per gene (input to k_main)
__device__ uint4 g_UWh[20000 * 32];       // fp16: uint4 at [g*32 + h*16 + j] = UW[g][j][8h..8h+7]

// ---------------------------------------------------------------------------
// Kernel 1 (fused): blocks 0..15 compute MW[j]+bb; blocks 16.. run gene MLP
// with one thread per gene (R6 version — best measured).
// ---------------------------------------------------------------------------
__global__ void k_pre(const float* __restrict__ BW, const float* __restrict__ BD,
                      const float* __restrict__ Wc1, const float* __restrict__ bc1,
                      const float* __restrict__ Boff,
                      const float* __restrict__ emb,
                      const float* __restrict__ W1, const float* __restrict__ b1,
                      const float* __restrict__ W2, const float* __restrict__ b2,
                      const float* __restrict__ W3, const float* __restrict__ b3,
                      int genes) {
    int t = threadIdx.x;

    if (blockIdx.x < 16) {
        __shared__ float sBW[4096], sBD[256], sWc1[256];
        {
            const float4* s = (const float4*)BW;
            float4* d = (float4*)sBW;
#pragma unroll
            for (int q = 0; q < 4; q++) d[t + 256 * q] = s[t + 256 * q];
            if (t < 64)       ((float4*)sBD)[t]       = ((const float4*)BD)[t];
            else if (t < 128) ((float4*)sWc1)[t - 64] = ((const float4*)Wc1)[t - 64];
        }
        __syncthreads();

        int j = blockIdx.x;
        int k = t >> 4, l = t & 15;
        float s = 0.f;
#pragma unroll
        for (int n = 0; n < 16; n++) {
            float wjn = sWc1[j * 16 + n];
#pragma unroll
            for (int m = 0; m < 16; m++) {
                float p = wjn * sBD[n * 16 + m];
                s = fmaf(p * sBW[n * 256 + m * 16 + k], sBW[m * 256 + n * 16 + l], s);
            }
        }
        g_MW[j * 256 + t] = s;

        if (blockIdx.x == 0 && t < 16) {
            float b = bc1[t];
#pragma unroll
            for (int n = 0; n < 16; n++) b = fmaf(sWc1[t * 16 + n], Boff[n], b);
            g_bb[t] = b;
        }
        return;
    }

    __shared__ float sW1[256], sW2[256], sW3[256], sb[48];
    if (t < 64)        ((float4*)sW1)[t]       = ((const float4*)W1)[t];
    else if (t < 128)  ((float4*)sW2)[t - 64]  = ((const float4*)W2)[t - 64];
    else if (t < 192)  ((float4*)sW3)[t - 128] = ((const float4*)W3)[t - 128];
    else if (t < 208) { int i = t - 192; sb[i] = b1[i]; sb[16 + i] = b2[i]; sb[32 + i] = b3[i]; }
    __syncthreads();

    int g = (blockIdx.x - 16) * 256 + t;
    if (g >= genes) return;

    float v[16], h[16], o[16];
    {
        const float4* ep = (const float4*)(emb + (size_t)g * 16);
        float4 a = ep[0], b = ep[1], c = ep[2], dd = ep[3];
        v[0]=a.x; v[1]=a.y; v[2]=a.z; v[3]=a.w;
        v[4]=b.x; v[5]=b.y; v[6]=b.z; v[7]=b.w;
        v[8]=c.x; v[9]=c.y; v[10]=c.z; v[11]=c.w;
        v[12]=dd.x; v[13]=dd.y; v[14]=dd.z; v[15]=dd.w;
    }
#pragma unroll
    for (int i = 0; i < 16; i++) {
        float s = sb[i];
#pragma unroll
        for (int jj = 0; jj < 16; jj++) s = fmaf(sW1[i * 16 + jj], v[jj], s);
        h[i] = fmaxf(s, 0.f);
    }
#pragma unroll
    for (int i = 0; i < 16; i++) {
        float s = sb[16 + i];
#pragma unroll
        for (int jj = 0; jj < 16; jj++) s = fmaf(sW2[i * 16 + jj], h[jj], s);
        o[i] = fmaxf(s, 0.f);
    }
#pragma unroll
    for (int i = 0; i < 16; i++) {
        float s = sb[32 + i];
#pragma unroll
        for (int jj = 0; jj < 16; jj++) s = fmaf(sW3[i * 16 + jj], o[jj], s);
        v[i] = s;   // no relu on layer 3
    }

    float4* fp = (float4*)(g_E3f + (size_t)g * 16);
    fp[0] = make_float4(v[0], v[1], v[2], v[3]);
    fp[1] = make_float4(v[4], v[5], v[6], v[7]);
    fp[2] = make_float4(v[8], v[9], v[10], v[11]);
    fp[3] = make_float4(v[12], v[13], v[14], v[15]);

    uint4 hv[2];
    unsigned* hw = (unsigned*)hv;
#pragma unroll
    for (int q = 0; q < 8; q++) {
        __half2 p = __floats2half2_rn(v[2 * q], v[2 * q + 1]);
        hw[q] = *(unsigned*)&p;
    }
    g_E3h[(size_t)g * 2 + 0] = hv[0];
    g_E3h[(size_t)g * 2 + 1] = hv[1];
}

// ---------------------------------------------------------------------------
// Kernel 2: UW[g,j,k] = sum_l MW[j,k,l]*E3[g,l], fp16 output.
// R6 compute; store index adjusted for the uint4-friendly layout.
// ---------------------------------------------------------------------------
__global__ void k_uw(int genes) {
    __shared__ float sv[GBLK * 17];
    int t = threadIdx.x;
    int base = blockIdx.x * GBLK;

    {
        int fidx = base * 4 + t;
        int gl = t >> 2, q = t & 3;
        float4 v = make_float4(0.f, 0.f, 0.f, 0.f);
        if (fidx < genes * 4) v = ((const float4*)g_E3f)[fidx];
        sv[gl * 17 + q * 4 + 0] = v.x;
        sv[gl * 17 + q * 4 + 1] = v.y;
        sv[gl * 17 + q * 4 + 2] = v.z;
        sv[gl * 17 + q * 4 + 3] = v.w;
    }

    int j = t & 15;
    int c = (t >> 4) & 3;
    int sg = t >> 6;

    float mw[64];
    {
        const float4* mp = (const float4*)(g_MW + j * 256 + c * 64);
#pragma unroll
        for (int q = 0; q < 16; q++) {
            float4 m4 = mp[q];
            mw[q*4+0]=m4.x; mw[q*4+1]=m4.y; mw[q*4+2]=m4.z; mw[q*4+3]=m4.w;
        }
    }
    __syncthreads();

    uint2* outp = (uint2*)g_UWh;
#pragma unroll
    for (int gi = 0; gi < 16; gi++) {
        int gl = gi * 4 + sg;
        int g = base + gl;
        float u0 = 0.f, u1 = 0.f, u2 = 0.f, u3 = 0.f;
#pragma unroll
        for (int l = 0; l < 16; l++) {
            float ev = sv[gl * 17 + l];
            u0 = fmaf(mw[0  + l], ev, u0);
            u1 = fmaf(mw[16 + l], ev, u1);
            u2 = fmaf(mw[32 + l], ev, u2);
            u3 = fmaf(mw[48 + l], ev, u3);
        }
        if (g < genes) {
            __half2 h01 = __floats2half2_rn(u0, u1);
            __half2 h23 = __floats2half2_rn(u2, u3);
            uint2 v;
            v.x = *(unsigned*)&h01;
            v.y = *(unsigned*)&h23;
            // uint4 layout: uint2 index = g*64 + (c>>1)*32 + j*2 + (c&1)
            outp[(size_t)g * 64 + (c >> 1) * 32 + j * 2 + (c & 1)] = v;
        }
    }
}

// ---------------------------------------------------------------------------
// Kernel 3: main. 4 rows per 16-lane group (64 rows/block); lane j owns unit j.
//   y_j = relu(E3h[x0] . UWh[x1,j,:] + bb[j]); out = sum_j Wc2[j]*y_j + bc2 + sum(phenos)
// ---------------------------------------------------------------------------
__global__ void k_main(const int* __restrict__ x, const float* __restrict__ phenos,
                       const float* __restrict__ Wc2, const float* __restrict__ bc2,
                       float* __restrict__ out) {
    int t = threadIdx.x;
    int j = t & 15;
    int grp = t >> 4;
    int rbase = blockIdx.x * 64 + grp;

    float bbj = g_bb[j];
    float wc = Wc2[j];
    float acc[4];

#pragma unroll
    for (int r = 0; r < 4; r++) {
        int row = rbase + 16 * r;
        int2 xi = ((const int2*)x)[row];
        const uint4* E = g_E3h + (size_t)xi.x * 2;
        uint4 e0 = E[0], e1 = E[1];
        const uint4* U = g_UWh + (size_t)xi.y * 32;
        uint4 ua = U[j], ub = U[16 + j];

        float z = bbj;
        unsigned ue[8] = {e0.x, e0.y, e0.z, e0.w, e1.x, e1.y, e1.z, e1.w};
        unsigned uu[8] = {ua.x, ua.y, ua.z, ua.w, ub.x, ub.y, ub.z, ub.w};
#pragma unroll
        for (int q = 0; q < 8; q++) {
            float2 a = __half22float2(*(__half2*)&ue[q]);
            float2 u = __half22float2(*(__half2*)&uu[q]);
            z = fmaf(a.x, u.x, z);
            z = fmaf(a.y, u.y, z);
        }
        acc[r] = fmaxf(z, 0.f) * wc;
    }

#pragma unroll
    for (int m = 8; m >= 1; m >>= 1) {
#pragma unroll
        for (int r = 0; r < 4; r++)
            acc[r] += __shfl_xor_sync(0xffffffffu, acc[r], m);
    }

    if (j == 0) {
        float bc = bc2[0];
#pragma unroll
        for (int r = 0; r < 4; r++) {
            int row = rbase + 16 * r;
            float2 p = ((const float2*)phenos)[row];
            out[row] = acc[r] + bc + p.x + p.y;
        }
    }
}

// ---------------------------------------------------------------------------
extern "C" void kernel_launch(void* const* d_in, const int* in_sizes, int n_in,
                              void* d_out, int out_size) {
    const int*   x      = (const int*)d_in[0];
    const float* phenos = (const float*)d_in[1];
    const float* emb    = (const float*)d_in[2];
    const float* W1 = (const float*)d_in[3],  *b1 = (const float*)d_in[4];
    const float* W2 = (const float*)d_in[5],  *b2 = (const float*)d_in[6];
    const float* W3 = (const float*)d_in[7],  *b3 = (const float*)d_in[8];
    const float* BW = (const float*)d_in[9],  *BD = (const float*)d_in[10];
    const float* Boff = (const float*)d_in[11];
    const float* Wc1 = (const float*)d_in[12], *bc1 = (const float*)d_in[13];
    const float* Wc2 = (const float*)d_in[14], *bc2 = (const float*)d_in[15];
    float* out = (float*)d_out;

    int rows  = in_sizes[0] / 2;     // 262144
    int genes = in_sizes[2] / D;     // 20000

    int eblocks = (genes + 255) / 256;                // 79
    k_pre<<<16 + eblocks, 256>>>(BW, BD, Wc1, bc1, Boff, emb,
                                 W1, b1, W2, b2, W3, b3, genes);
    k_uw<<<(genes + GBLK - 1) / GBLK, 256>>>(genes);
    k_main<<<rows / 64, 256>>>(x, phenos, Wc2, bc2, out);
}